// round 16
// baseline (speedup 1.0000x reference)
#include <cuda_runtime.h>
#include <cuda_fp16.h>
#include <mma.h>
#include <cstddef>
#include <cstdint>

using namespace nvcuda;

#define LLAYERS 6
#define BB 4
#define NN 1024
#define DD 1024
#define HH 16
#define HDIM 64
#define FF 4096
#define MTOK (BB * NN)      /* 4096 */
#define LN_EPS 1e-5f

// ---------------- scratch (no allocations allowed) ----------------
__device__ float  g_Y[(size_t)MTOK * DD];
__device__ float  g_Y1[(size_t)LLAYERS * MTOK * DD];
__device__ int    g_maskNZ[2];       // [0]=src_mask nonzero, [1]=trg_mask nonzero
// fp16 mirrors
__device__ __half h_wq1[(size_t)LLAYERS * DD * DD];
__device__ __half h_wo1[(size_t)LLAYERS * DD * DD];
__device__ __half h_wq2[(size_t)LLAYERS * DD * DD];
__device__ __half h_wo2[(size_t)LLAYERS * DD * DD];
__device__ __half h_wf1[(size_t)LLAYERS * FF * DD];
__device__ __half h_wf2[(size_t)LLAYERS * DD * FF];
__device__ __half h_feats[(size_t)LLAYERS * MTOK * DD];
__device__ __half h_enc[(size_t)MTOK * DD];
// packed KV weights / biases
__device__ __half h_KV1w[(size_t)LLAYERS * 2 * DD * DD];
__device__ __half h_KV2w[(size_t)LLAYERS * 2 * DD * DD];
__device__ float  g_bKV1[(size_t)LLAYERS * 2 * DD];
__device__ float  g_bKV2[(size_t)LLAYERS * 2 * DD];
// activations
__device__ __half h_KV1[(size_t)LLAYERS * MTOK * 2 * DD];
__device__ __half h_Q1[(size_t)LLAYERS * MTOK * DD];
__device__ __half h_Q2[(size_t)LLAYERS * MTOK * DD];
__device__ __half h_T1[(size_t)LLAYERS * MTOK * DD];
__device__ __half h_Yh1[(size_t)LLAYERS * MTOK * DD];
__device__ __half h_KV2[(size_t)MTOK * 2 * DD];
__device__ __half h_T[(size_t)MTOK * DD];
__device__ __half h_Yh[(size_t)MTOK * DD];
__device__ __half h_X[(size_t)MTOK * DD];
__device__ __half h_Hb[(size_t)MTOK * FF];

// ---------------- cp.async helpers ----------------
__device__ __forceinline__ void cp16(void* sptr, const void* gptr) {
    uint32_t sa = (uint32_t)__cvta_generic_to_shared(sptr);
    asm volatile("cp.async.cg.shared.global [%0], [%1], 16;\n" :: "r"(sa), "l"(gptr));
}
#define CP_COMMIT() asm volatile("cp.async.commit_group;\n" ::: "memory")
#define CP_WAIT_0() asm volatile("cp.async.wait_group 0;\n" ::: "memory")
#define CP_WAIT_1() asm volatile("cp.async.wait_group 1;\n" ::: "memory")

// ---------------- raw mma / ldmatrix helpers (attention) ----------------
__device__ __forceinline__ void mma16816(float* d, const uint32_t* a, const uint32_t* b) {
    asm volatile(
        "mma.sync.aligned.m16n8k16.row.col.f32.f16.f16.f32 "
        "{%0,%1,%2,%3}, {%4,%5,%6,%7}, {%8,%9}, {%0,%1,%2,%3};\n"
        : "+f"(d[0]), "+f"(d[1]), "+f"(d[2]), "+f"(d[3])
        : "r"(a[0]), "r"(a[1]), "r"(a[2]), "r"(a[3]), "r"(b[0]), "r"(b[1]));
}
__device__ __forceinline__ void ldsm4(uint32_t* r, uint32_t addr) {
    asm volatile("ldmatrix.sync.aligned.m8n8.x4.shared.b16 {%0,%1,%2,%3}, [%4];\n"
        : "=r"(r[0]), "=r"(r[1]), "=r"(r[2]), "=r"(r[3]) : "r"(addr));
}
__device__ __forceinline__ void ldsm4t(uint32_t* r, uint32_t addr) {
    asm volatile("ldmatrix.sync.aligned.m8n8.x4.trans.shared.b16 {%0,%1,%2,%3}, [%4];\n"
        : "=r"(r[0]), "=r"(r[1]), "=r"(r[2]), "=r"(r[3]) : "r"(addr));
}
__device__ __forceinline__ uint32_t h2pack(float a, float b) {
    __half2 h = __floats2half2_rn(a, b);
    return *(uint32_t*)&h;
}

// =====================================================================
// Conversion / packing / mask-check kernels
// =====================================================================
__global__ __launch_bounds__(256) void cvt_f2h(
    const float* __restrict__ s, __half* __restrict__ d, long n)
{
    long i = ((long)blockIdx.x * 256 + threadIdx.x) * 8;
    if (i >= n) return;
    float4 a = *(const float4*)(s + i);
    float4 b = *(const float4*)(s + i + 4);
    uint4 u;
    ((__half2*)&u)[0] = __floats2half2_rn(a.x, a.y);
    ((__half2*)&u)[1] = __floats2half2_rn(a.z, a.w);
    ((__half2*)&u)[2] = __floats2half2_rn(b.x, b.y);
    ((__half2*)&u)[3] = __floats2half2_rn(b.z, b.w);
    *(uint4*)(d + i) = u;
}

__global__ __launch_bounds__(256) void pack_w(
    const float* __restrict__ a, const float* __restrict__ b,
    __half* __restrict__ dst, long perL)
{
    long i = ((long)blockIdx.x * 256 + threadIdx.x) * 8;
    long l = i / (2 * perL);
    long r = i - l * 2 * perL;
    const float* src = (r < perL) ? a + l * perL + r : b + l * perL + (r - perL);
    float4 x = *(const float4*)(src);
    float4 y = *(const float4*)(src + 4);
    uint4 u;
    ((__half2*)&u)[0] = __floats2half2_rn(x.x, x.y);
    ((__half2*)&u)[1] = __floats2half2_rn(x.z, x.w);
    ((__half2*)&u)[2] = __floats2half2_rn(y.x, y.y);
    ((__half2*)&u)[3] = __floats2half2_rn(y.z, y.w);
    *(uint4*)(dst + i) = u;
}

__global__ __launch_bounds__(256) void pack_b(
    const float* __restrict__ a, const float* __restrict__ b,
    float* __restrict__ dst, long perL)
{
    long i = ((long)blockIdx.x * 256 + threadIdx.x) * 4;
    long l = i / (2 * perL);
    long r = i - l * 2 * perL;
    const float* src = (r < perL) ? a + l * perL + r : b + l * perL + (r - perL);
    *(float4*)(dst + i) = *(const float4*)src;
}

__global__ void zero_flags() { g_maskNZ[0] = 0; g_maskNZ[1] = 0; }

__global__ __launch_bounds__(256) void mask_check(
    const float* __restrict__ m, long n, int idx)
{
    long i = ((long)blockIdx.x * 256 + threadIdx.x) * 4;
    if (i >= n) return;
    float4 v = *(const float4*)(m + i);
    if (v.x != 0.f || v.y != 0.f || v.z != 0.f || v.w != 0.f)
        atomicOr(&g_maskNZ[idx], 1);
}

// =====================================================================
// f16 TC GEMM — round-10 wmma version (best measured; at register roof).
// =====================================================================
#define GBKH 64
#define GSTH 72
#define GBUFH (128 * GSTH)
#define GEMM_SMEM_BYTES (4 * GBUFH * 2)   /* 73728 B */

__global__ __launch_bounds__(256, 2) void gemm_h(
    const __half* __restrict__ A, const __half* __restrict__ W,
    const float* __restrict__ bias, const float* __restrict__ res,
    float* __restrict__ C, __half* __restrict__ Ch,
    int M, int N, int K, int doRelu, int ldc)
{
    extern __shared__ char dynb[];
    __half* hsm = (__half*)dynb;
    __shared__ float stage[8][16 * 16];

    const int tid  = threadIdx.x;
    const int warp = tid >> 5;
    const int lane = tid & 31;
    const int wm   = warp >> 2;
    const int wn   = warp & 3;

    const __half* Ab = A + (size_t)blockIdx.y * 128 * K;
    const __half* Wb = W + (size_t)blockIdx.x * 128 * K;
    const int KT = K / GBKH;

    wmma::fragment<wmma::accumulator, 16, 16, 16, float> acc[4][2];
#pragma unroll
    for (int i = 0; i < 4; i++)
#pragma unroll
        for (int j = 0; j < 2; j++) wmma::fill_fragment(acc[i][j], 0.f);

    {
        __half* As = hsm;
        __half* Ws = hsm + GBUFH;
#pragma unroll
        for (int t = 0; t < 4; t++) {
            int c = tid + t * 256;
            int row = c >> 3, col8 = c & 7;
            cp16(As + row * GSTH + col8 * 8, Ab + (size_t)row * K + col8 * 8);
            cp16(Ws + row * GSTH + col8 * 8, Wb + (size_t)row * K + col8 * 8);
        }
        CP_COMMIT();
    }

    for (int kt = 0; kt < KT; kt++) {
        if (kt + 1 < KT) {
            __half* As = hsm + ((kt + 1) & 1) * 2 * GBUFH;
            __half* Ws = As + GBUFH;
            const int k0 = (kt + 1) * GBKH;
#pragma unroll
            for (int t = 0; t < 4; t++) {
                int c = tid + t * 256;
                int row = c >> 3, col8 = c & 7;
                cp16(As + row * GSTH + col8 * 8, Ab + (size_t)row * K + k0 + col8 * 8);
                cp16(Ws + row * GSTH + col8 * 8, Wb + (size_t)row * K + k0 + col8 * 8);
            }
            CP_COMMIT();
            CP_WAIT_1();
        } else {
            CP_WAIT_0();
        }
        __syncthreads();

        const __half* As = hsm + (kt & 1) * 2 * GBUFH;
        const __half* Ws = As + GBUFH;
#pragma unroll
        for (int kk = 0; kk < 4; kk++) {
            wmma::fragment<wmma::matrix_a, 16, 16, 16, __half, wmma::row_major> af[4];
            wmma::fragment<wmma::matrix_b, 16, 16, 16, __half, wmma::col_major> bf[2];
#pragma unroll
            for (int i = 0; i < 4; i++)
                wmma::load_matrix_sync(af[i], &As[(wm * 64 + i * 16) * GSTH + kk * 16], GSTH);
#pragma unroll
            for (int j = 0; j < 2; j++)
                wmma::load_matrix_sync(bf[j], &Ws[(wn * 32 + j * 16) * GSTH + kk * 16], GSTH);
#pragma unroll
            for (int i = 0; i < 4; i++)
#pragma unroll
                for (int j = 0; j < 2; j++)
                    wmma::mma_sync(acc[i][j], af[i], bf[j], acc[i][j]);
        }
        __syncthreads();
    }

#pragma unroll
    for (int i = 0; i < 4; i++) {
#pragma unroll
        for (int j = 0; j < 2; j++) {
            wmma::store_matrix_sync(stage[warp], acc[i][j], 16, wmma::mem_row_major);
            __syncwarp();
            int r0 = blockIdx.y * 128 + wm * 64 + i * 16;
            int c0 = blockIdx.x * 128 + wn * 32 + j * 16;
#pragma unroll
            for (int e = 0; e < 2; e++) {
                int idx = lane + e * 32;
                int rr  = idx >> 2;
                int cc  = (idx & 3) << 2;
                float4 v  = *(float4*)&stage[warp][rr * 16 + cc];
                float4 b4 = *(const float4*)(bias + c0 + cc);
                v.x += b4.x; v.y += b4.y; v.z += b4.z; v.w += b4.w;
                size_t row = (size_t)(r0 + rr);
                if (res) {
                    float4 r = *(const float4*)(res + row * ldc + c0 + cc);
                    v.x += r.x; v.y += r.y; v.z += r.z; v.w += r.w;
                }
                if (doRelu) {
                    v.x = fmaxf(v.x, 0.f); v.y = fmaxf(v.y, 0.f);
                    v.z = fmaxf(v.z, 0.f); v.w = fmaxf(v.w, 0.f);
                }
                if (C) *(float4*)(C + row * ldc + c0 + cc) = v;
                if (Ch) {
                    uint2 u;
                    ((__half2*)&u)[0] = __floats2half2_rn(v.x, v.y);
                    ((__half2*)&u)[1] = __floats2half2_rn(v.z, v.w);
                    *(uint2*)(Ch + row * ldc + c0 + cc) = u;
                }
            }
            __syncwarp();
        }
    }
}

// =====================================================================
// Flash attention v5 (round-15): register-resident FA2 + mask elision.
// grid: (N/128, B*H)
// =====================================================================
#define AQ_ST 72
#define ATQ_OFF 0
#define ATK_OFF(s) (18432 + (s) * 9216)
#define ATV_OFF(s) (46080 + (s) * 9216)
#define ATT_SMEM_BYTES 73728

__global__ __launch_bounds__(256, 2) void attn_h(
    const __half* __restrict__ Q, const __half* __restrict__ Kb,
    const __half* __restrict__ V, __half* __restrict__ T,
    const float* __restrict__ mask, int ldkv,
    const int* __restrict__ nzflag)
{
    extern __shared__ char dynb[];
    const uint32_t sb = (uint32_t)__cvta_generic_to_shared(dynb);

    const int z = blockIdx.y;
    const int b = z >> 4, hh = z & 15;
    const __half* Qz = Q  + (size_t)b * NN * DD   + hh * HDIM;
    const __half* Kz = Kb + (size_t)b * NN * ldkv + hh * HDIM;
    const __half* Vz = V  + (size_t)b * NN * ldkv + hh * HDIM;
    __half*       Tz = T  + (size_t)b * NN * DD   + hh * HDIM;
    const int i0 = blockIdx.x * 128;

    const int tid  = threadIdx.x;
    const int warp = tid >> 5;
    const int lane = tid & 31;
    const int g    = lane >> 2;
    const int t    = lane & 3;
    const int q    = lane >> 3;
    const int qr   = lane & 7;

    const int useMask = *nzflag;

    const uint32_t qlane = (uint32_t)(((q & 1) * 8 + qr + warp * 16) * 144 + (q >> 1) * 16);
    const uint32_t klane = (uint32_t)(((q >> 1) * 8 + qr) * 144 + (q & 1) * 16);
    const uint32_t vlane = (uint32_t)(((q & 1) * 8 + qr) * 144 + (q >> 1) * 16);

    const float* mrow0 = mask + (size_t)(i0 + warp * 16 + g) * NN;
    const float* mrow1 = mrow0 + 8 * NN;

    {
        __half* Qs = (__half*)(dynb + ATQ_OFF);
#pragma unroll
        for (int c0 = 0; c0 < 4; c0++) {
            int c = tid + c0 * 256;
            int row = c >> 3, col8 = c & 7;
            cp16(Qs + row * AQ_ST + col8 * 8, Qz + (size_t)(i0 + row) * DD + col8 * 8);
        }
        __half* Ks = (__half*)(dynb + ATK_OFF(0));
        __half* Vs = (__half*)(dynb + ATV_OFF(0));
#pragma unroll
        for (int c0 = 0; c0 < 2; c0++) {
            int c = tid + c0 * 256;
            int row = c >> 3, col8 = c & 7;
            cp16(Ks + row * AQ_ST + col8 * 8, Kz + (size_t)row * ldkv + col8 * 8);
            cp16(Vs + row * AQ_ST + col8 * 8, Vz + (size_t)row * ldkv + col8 * 8);
        }
        CP_COMMIT();
        Ks = (__half*)(dynb + ATK_OFF(1));
        Vs = (__half*)(dynb + ATV_OFF(1));
#pragma unroll
        for (int c0 = 0; c0 < 2; c0++) {
            int c = tid + c0 * 256;
            int row = c >> 3, col8 = c & 7;
            cp16(Ks + row * AQ_ST + col8 * 8, Kz + (size_t)(64 + row) * ldkv + col8 * 8);
            cp16(Vs + row * AQ_ST + col8 * 8, Vz + (size_t)(64 + row) * ldkv + col8 * 8);
        }
        CP_COMMIT();
    }

    CP_WAIT_1();
    __syncthreads();

    uint32_t qa[4][4];
#pragma unroll
    for (int kk = 0; kk < 4; kk++)
        ldsm4(qa[kk], sb + ATQ_OFF + qlane + kk * 32);

    float o[8][4];
#pragma unroll
    for (int i = 0; i < 8; i++) { o[i][0] = o[i][1] = o[i][2] = o[i][3] = 0.f; }
    float m0 = -1e30f, m1 = -1e30f, sr0 = 0.f, sr1 = 0.f;

    const int J = NN / 64;
    for (int j0 = 0; j0 < J; j0++) {
        if (j0 > 0) {
            if (j0 + 1 < J) { CP_WAIT_1(); } else { CP_WAIT_0(); }
            __syncthreads();
        }
        if (j0 + 2 < J) {
            const int st = (j0 + 2) % 3;
            __half* Ks = (__half*)(dynb + ATK_OFF(st));
            __half* Vs = (__half*)(dynb + ATV_OFF(st));
            const size_t rbase = (size_t)(j0 + 2) * 64;
#pragma unroll
            for (int c0 = 0; c0 < 2; c0++) {
                int c = tid + c0 * 256;
                int row = c >> 3, col8 = c & 7;
                cp16(Ks + row * AQ_ST + col8 * 8, Kz + (rbase + row) * ldkv + col8 * 8);
                cp16(Vs + row * AQ_ST + col8 * 8, Vz + (rbase + row) * ldkv + col8 * 8);
            }
            CP_COMMIT();
        }

        const uint32_t ksb = sb + ATK_OFF(j0 % 3);
        const uint32_t vsb = sb + ATV_OFF(j0 % 3);

        float s[8][4];
#pragma unroll
        for (int i = 0; i < 8; i++) { s[i][0] = s[i][1] = s[i][2] = s[i][3] = 0.f; }
#pragma unroll
        for (int nt2 = 0; nt2 < 4; nt2++) {
#pragma unroll
            for (int kk = 0; kk < 4; kk++) {
                uint32_t kb[4];
                ldsm4(kb, ksb + (uint32_t)(nt2 * 2304 + kk * 32) + klane);
                mma16816(s[2 * nt2],     qa[kk], kb);
                mma16816(s[2 * nt2 + 1], qa[kk], kb + 2);
            }
        }

        float mx0 = m0, mx1 = m1;
        if (useMask) {
#pragma unroll
            for (int nt = 0; nt < 8; nt++) {
                int col = j0 * 64 + nt * 8 + 2 * t;
                float2 k0 = *(const float2*)(mrow0 + col);
                float2 k1 = *(const float2*)(mrow1 + col);
                s[nt][0] = fmaf(s[nt][0], 0.125f, k0.x);
                s[nt][1] = fmaf(s[nt][1], 0.125f, k0.y);
                s[nt][2] = fmaf(s[nt][2], 0.125f, k1.x);
                s[nt][3] = fmaf(s[nt][3], 0.125f, k1.y);
                mx0 = fmaxf(mx0, fmaxf(s[nt][0], s[nt][1]));
                mx1 = fmaxf(mx1, fmaxf(s[nt][2], s[nt][3]));
            }
        } else {
#pragma unroll
            for (int nt = 0; nt < 8; nt++) {
                s[nt][0] *= 0.125f; s[nt][1] *= 0.125f;
                s[nt][2] *= 0.125f; s[nt][3] *= 0.125f;
                mx0 = fmaxf(mx0, fmaxf(s[nt][0], s[nt][1]));
                mx1 = fmaxf(mx1, fmaxf(s[nt][2], s[nt][3]));
            }
        }
        mx0 = fmaxf(mx0, __shfl_xor_sync(0xffffffffu, mx0, 1));
        mx0 = fmaxf(mx0, __shfl_xor_sync(0xffffffffu, mx0, 2));
        mx1 = fmaxf(mx1, __shfl_xor_sync(0xffffffffu, mx1, 1));
        mx1 = fmaxf(mx1, __shfl_xor_sync(0xffffffffu, mx1, 2));
        const float c0 = __expf(m0 - mx0);
        const float c1 = __expf(m1 - mx1);

        uint32_t pa[4][4];
        float sum0 = 0.f, sum1 = 0.f;
#pragma unroll
        for (int nt = 0; nt < 8; nt++) {
            float p0 = __expf(s[nt][0] - mx0);
            float p1 = __expf(s[nt][1] - mx0);
            float p2 = __expf(s[nt][2] - mx1);
            float p3 = __expf(s[nt][3] - mx1);
            sum0 += p0 + p1; sum1 += p2 + p3;
            pa[nt >> 1][(nt & 1) * 2 + 0] = h2pack(p0, p1);
            pa[nt >> 1][(nt & 1) * 2 + 1] = h2pack(p2, p3);
        }
        sum0 += __shfl_xor_sync(0xffffffffu, sum0, 1);
        sum0 += __shfl_xor_sync(0xffffffffu, sum0, 2);
        sum1 += __shfl_xor_sync(0xffffffffu, sum1, 1);
        sum1 += __shfl_xor_sync(0xffffffffu, sum1, 2);
        sr0 = sr0 * c0 + sum0;
        sr1 = sr1 * c1 + sum1;
        m0 = mx0; m1 = mx1;
#pragma unroll
        for (int nt = 0; nt < 8; nt++) {
            o[nt][0] *= c0; o[nt][1] *= c0;
            o[nt][2] *= c1; o[nt][3] *= c1;
        }

#pragma unroll
        for (int nt2 = 0; nt2 < 4; nt2++) {
#pragma unroll
            for (int kt = 0; kt < 4; kt++) {
                uint32_t vb[4];
                ldsm4t(vb, vsb + (uint32_t)(kt * 2304 + nt2 * 32) + vlane);
                mma16816(o[2 * nt2],     pa[kt], vb);
                mma16816(o[2 * nt2 + 1], pa[kt], vb + 2);
            }
        }
    }

    const float inv0 = 1.f / sr0;
    const float inv1 = 1.f / sr1;
    __half* tr0 = Tz + (size_t)(i0 + warp * 16 + g) * DD + 2 * t;
    __half* tr1 = tr0 + 8 * DD;
#pragma unroll
    for (int nt = 0; nt < 8; nt++) {
        uint32_t u0 = h2pack(o[nt][0] * inv0, o[nt][1] * inv0);
        uint32_t u1 = h2pack(o[nt][2] * inv1, o[nt][3] * inv1);
        *(uint32_t*)(tr0 + nt * 8) = u0;
        *(uint32_t*)(tr1 + nt * 8) = u1;
    }
}

// =====================================================================
// LayerNorm v2 (round-14): shuffle reductions, 1 barrier.
// =====================================================================
__global__ __launch_bounds__(256) void layernorm_row(
    const float* __restrict__ X, const float* __restrict__ g,
    const float* __restrict__ bta, float* __restrict__ Y,
    __half* __restrict__ Yh)
{
    __shared__ float psum[8], psq[8];
    const size_t base = (size_t)blockIdx.x * DD;
    const int tid  = threadIdx.x;
    const int warp = tid >> 5;
    const int lane = tid & 31;
    float4 v = *(const float4*)(X + base + tid * 4);

    float s  = v.x + v.y + v.z + v.w;
    float sq = v.x * v.x + v.y * v.y + v.z * v.z + v.w * v.w;
#pragma unroll
    for (int o = 16; o > 0; o >>= 1) {
        s  += __shfl_xor_sync(0xffffffffu, s,  o);
        sq += __shfl_xor_sync(0xffffffffu, sq, o);
    }
    if (lane == 0) { psum[warp] = s; psq[warp] = sq; }
    __syncthreads();

    float ts = 0.f, tq = 0.f;
#pragma unroll
    for (int w = 0; w < 8; w++) { ts += psum[w]; tq += psq[w]; }
    const float mean = ts * (1.f / DD);
    const float var  = tq * (1.f / DD) - mean * mean;
    const float inv  = rsqrtf(var + LN_EPS);

    float4 gg = *(const float4*)(g + tid * 4);
    float4 bb = *(const float4*)(bta + tid * 4);
    float4 o;
    o.x = (v.x - mean) * inv * gg.x + bb.x;
    o.y = (v.y - mean) * inv * gg.y + bb.y;
    o.z = (v.z - mean) * inv * gg.z + bb.z;
    o.w = (v.w - mean) * inv * gg.w + bb.w;
    *(float4*)(Y + base + tid * 4) = o;
    if (Yh) {
        uint2 u;
        ((__half2*)&u)[0] = __floats2half2_rn(o.x, o.y);
        ((__half2*)&u)[1] = __floats2half2_rn(o.z, o.w);
        *(uint2*)(Yh + base + tid * 4) = u;
    }
}

// =====================================================================
// Host orchestration: triple-stream. s2 = phase A, s3 = B-set
// conversions (concurrent with stream-0 A-rest conversions), stream 0 =
// phase B with KV2 hoisted before the evL wait.
// =====================================================================
static inline void cvt0(const float* src, __half* dst, long n, cudaStream_t st) {
    cvt_f2h<<<(unsigned)(n / 2048), 256, 0, st>>>(src, dst, n);
}

extern "C" void kernel_launch(void* const* d_in, const int* in_sizes, int n_in,
                              void* d_out, int out_size)
{
    const float* feats    = (const float*)d_in[0];
    const float* enc      = (const float*)d_in[1];
    const float* trg_mask = (const float*)d_in[2];
    const float* src_mask = (const float*)d_in[3];
    const float* wq1 = (const float*)d_in[4];  const float* bq1 = (const float*)d_in[5];
    const float* wk1 = (const float*)d_in[6];  const float* bk1 = (const float*)d_in[7];
    const float* wv1 = (const float*)d_in[8];  const float* bv1 = (const float*)d_in[9];
    const float* wo1 = (const float*)d_in[10]; const float* bo1 = (const float*)d_in[11];
    const float* wq2 = (const float*)d_in[12]; const float* bq2 = (const float*)d_in[13];
    const float* wk2 = (const float*)d_in[14]; const float* bk2 = (const float*)d_in[15];
    const float* wv2 = (const float*)d_in[16]; const float* bv2 = (const float*)d_in[17];
    const float* wo2 = (const float*)d_in[18]; const float* bo2 = (const float*)d_in[19];
    const float* wf1 = (const float*)d_in[20]; const float* bf1 = (const float*)d_in[21];
    const float* wf2 = (const float*)d_in[22]; const float* bf2 = (const float*)d_in[23];
    const float* g1  = (const float*)d_in[24]; const float* be1 = (const float*)d_in[25];
    const float* g2  = (const float*)d_in[26]; const float* be2 = (const float*)d_in[27];
    const float* g3  = (const float*)d_in[28]; const float* be3 = (const float*)d_in[29];
    float* out = (float*)d_out;

    static int init_done = 0;
    static cudaStream_t s2, s3;
    static cudaEvent_t evF, evA, evC;
    static cudaEvent_t evL[LLAYERS];
    if (!init_done) {
        cudaFuncSetAttribute(gemm_h,
            cudaFuncAttributeMaxDynamicSharedMemorySize, GEMM_SMEM_BYTES);
        cudaFuncSetAttribute(attn_h,
            cudaFuncAttributeMaxDynamicSharedMemorySize, ATT_SMEM_BYTES);
        int prLo = 0, prHi = 0;
        cudaDeviceGetStreamPriorityRange(&prLo, &prHi);
        cudaStreamCreateWithPriority(&s2, cudaStreamNonBlocking, prLo);
        cudaStreamCreateWithPriority(&s3, cudaStreamNonBlocking, prLo);
        cudaEventCreateWithFlags(&evF, cudaEventDisableTiming);
        cudaEventCreateWithFlags(&evA, cudaEventDisableTiming);
        cudaEventCreateWithFlags(&evC, cudaEventDisableTiming);
        for (int l = 0; l < LLAYERS; l++)
            cudaEventCreateWithFlags(&evL[l], cudaEventDisableTiming);
        init_done = 1;
    }

    float *Y, *Y1, *pbKV1, *pbKV2;
    int* pNZ;
    cudaGetSymbolAddress((void**)&Y,  g_Y);
    cudaGetSymbolAddress((void**)&Y1, g_Y1);
    cudaGetSymbolAddress((void**)&pbKV1, g_bKV1);
    cudaGetSymbolAddress((void**)&pbKV2, g_bKV2);
    cudaGetSymbolAddress((void**)&pNZ, g_maskNZ);
    __half *pwq1, *pwo1, *pwq2, *pwo2, *pwf1, *pwf2, *pfeats, *penc;
    __half *pKV1w, *pKV2w, *pKV1, *pQ1, *pQ2, *pT1, *pYh1, *pKV2, *pT, *pYh, *pX, *pHb;
    cudaGetSymbolAddress((void**)&pwq1, h_wq1);
    cudaGetSymbolAddress((void**)&pwo1, h_wo1);
    cudaGetSymbolAddress((void**)&pwq2, h_wq2);
    cudaGetSymbolAddress((void**)&pwo2, h_wo2);
    cudaGetSymbolAddress((void**)&pwf1, h_wf1);
    cudaGetSymbolAddress((void**)&pwf2, h_wf2);
    cudaGetSymbolAddress((void**)&pfeats, h_feats);
    cudaGetSymbolAddress((void**)&penc, h_enc);
    cudaGetSymbolAddress((void**)&pKV1w, h_KV1w);
    cudaGetSymbolAddress((void**)&pKV2w, h_KV2w);
    cudaGetSymbolAddress((void**)&pKV1, h_KV1);
    cudaGetSymbolAddress((void**)&pQ1, h_Q1);
    cudaGetSymbolAddress((void**)&pQ2, h_Q2);
    cudaGetSymbolAddress((void**)&pT1, h_T1);
    cudaGetSymbolAddress((void**)&pYh1, h_Yh1);
    cudaGetSymbolAddress((void**)&pKV2, h_KV2);
    cudaGetSymbolAddress((void**)&pT, h_T);
    cudaGetSymbolAddress((void**)&pYh, h_Yh);
    cudaGetSymbolAddress((void**)&pX, h_X);
    cudaGetSymbolAddress((void**)&pHb, h_Hb);

    const long nDD1 = (long)DD * DD;
    const long nMD1 = (long)MTOK * DD;
    const long nDD = (long)LLAYERS * nDD1;
    const long nFD = (long)LLAYERS * FF * DD;
    const long nMask = (long)NN * NN;

    // ---- mask pre-pass + minimal pre-fork conversions (stream 0) ----
    zero_flags<<<1, 1>>>();
    mask_check<<<(unsigned)(nMask / 1024), 256>>>(src_mask, nMask, 0);
    mask_check<<<(unsigned)(nMask / 1024), 256>>>(trg_mask, nMask, 1);
    cvt0(enc, penc, nMD1, 0);
    cvt0(feats, pfeats, nMD1, 0);
    cvt0(wq1, pwq1, nDD1, 0);
    cvt0(wo1, pwo1, nDD1, 0);
    cvt0(wq2, pwq2, nDD1, 0);
    pack_w<<<(unsigned)(2 * nDD1 / 2048), 256>>>(wk1, wv1, pKV1w, nDD1);
    pack_b<<<(unsigned)(2 * LLAYERS * DD / 1024), 256>>>(bk1, bv1, pbKV1, DD);

    dim3 blk(256);
    dim3 gD(DD / 128, MTOK / 128);
    dim3 gKV(2 * DD / 128, MTOK / 128);
    dim3 gF(FF / 128, MTOK / 128);
    dim3 gA(NN / 128, BB * HH);

    // ---- fork ----
    cudaEventRecord(evF, 0);
    cudaStreamWaitEvent(s2, evF, 0);
    cudaStreamWaitEvent(s3, evF, 0);

    // A-rest conversions on stream 0 (layers 1..5)
    cvt0(feats + nMD1, pfeats + nMD1, (LLAYERS - 1) * nMD1, 0);
    cvt0(wq1 + nDD1, pwq1 + nDD1, (LLAYERS - 1) * nDD1, 0);
    cvt0(wo1 + nDD1, pwo1 + nDD1, (LLAYERS - 1) * nDD1, 0);
    cvt0(wq2 + nDD1, pwq2 + nDD1, (LLAYERS - 1) * nDD1, 0);
    pack_w<<<(unsigned)(2 * (LLAYERS - 1) * nDD1 / 2048), 256>>>(
        wk1 + nDD1, wv1 + nDD1, pKV1w + 2 * nDD1, nDD1);
    cudaEventRecord(evA, 0);

    // B-set conversions on s3 (concurrent with A-rest)
    cvt0(wo2, pwo2, nDD, s3);
    cvt0(wf1, pwf1, nFD, s3);
    cvt0(wf2, pwf2, nFD, s3);
    pack_w<<<(unsigned)(2 * nDD / 2048), 256, 0, s3>>>(wk2, wv2, pKV2w, nDD1);
    pack_b<<<(unsigned)(2 * LLAYERS * DD / 1024), 256, 0, s3>>>(bk2, bv2, pbKV2, DD);
    cudaEventRecord(evC, s3);

    // ---- phase A (attn1 branch + q2 precompute) on s2 ----
    for (int l = 0; l < LLAYERS; l++) {
        const size_t wOff = (size_t)l * DD * DD;
        const size_t vOff = (size_t)l * DD;
        const size_t aOff = (size_t)l * MTOK * DD;
        const size_t kOff = (size_t)l * MTOK * 2 * DD;

        if (l == 1) cudaStreamWaitEvent(s2, evA, 0);

        gemm_h<<<gD, blk, GEMM_SMEM_BYTES, s2>>>(
            pfeats + aOff, pwq1 + wOff, bq1 + vOff, nullptr,
            nullptr, pQ1 + aOff, MTOK, DD, DD, 0, DD);
        gemm_h<<<gKV, blk, GEMM_SMEM_BYTES, s2>>>(
            penc, pKV1w + 2 * wOff, pbKV1 + 2 * vOff, nullptr,
            nullptr, pKV1 + kOff, MTOK, 2 * DD, DD, 0, 2 * DD);
        attn_h<<<gA, blk, ATT_SMEM_BYTES, s2>>>(
            pQ1 + aOff, pKV1 + kOff, pKV1 + kOff + DD, pT1 + aOff,
            src_mask, 2 * DD, pNZ + 0);
        gemm_h<<<gD, blk, GEMM_SMEM_BYTES, s2>>>(
            pT1 + aOff, pwo1 + wOff, bo1 + vOff, feats + aOff,
            Y1 + aOff, nullptr, MTOK, DD, DD, 0, DD);
        layernorm_row<<<MTOK, blk, 0, s2>>>(
            Y1 + aOff, g1 + vOff, be1 + vOff, Y1 + aOff, pYh1 + aOff);
        gemm_h<<<gD, blk, GEMM_SMEM_BYTES, s2>>>(
            pYh1 + aOff, pwq2 + wOff, bq2 + vOff, nullptr,
            nullptr, pQ2 + aOff, MTOK, DD, DD, 0, DD);
        cudaEventRecord(evL[l], s2);
    }

    // ---- phase B: serial decoder chain on stream 0 ----
    cudaStreamWaitEvent(0, evC, 0);   // B-set weights ready
    const __half* Xh = penc;
    for (int l = 0; l < LLAYERS; l++) {
        const size_t wOff = (size_t)l * DD * DD;
        const size_t fOff = (size_t)l * FF * DD;
        const size_t vOff = (size_t)l * DD;
        const size_t aOff = (size_t)l * MTOK * DD;

        // KV2 depends only on the previous layer's output — issue it
        // BEFORE waiting for phase A's layer-l results.
        gemm_h<<<gKV, blk, GEMM_SMEM_BYTES>>>(
            Xh, pKV2w + 2 * wOff, pbKV2 + 2 * vOff, nullptr,
            nullptr, pKV2, MTOK, 2 * DD, DD, 0, 2 * DD);

        cudaStreamWaitEvent(0, evL[l], 0);

        attn_h<<<gA, blk, ATT_SMEM_BYTES>>>(
            pQ2 + aOff, pKV2, pKV2 + DD, pT, trg_mask, 2 * DD, pNZ + 1);
        gemm_h<<<gD, blk, GEMM_SMEM_BYTES>>>(
            pT, pwo2 + wOff, bo2 + vOff, Y1 + aOff,
            Y, nullptr, MTOK, DD, DD, 0, DD);
        layernorm_row<<<MTOK, blk>>>(Y, g2 + vOff, be2 + vOff, Y, pYh);

        gemm_h<<<gF, blk, GEMM_SMEM_BYTES>>>(
            pYh, pwf1 + fOff, bf1 + (size_t)l * FF, nullptr,
            nullptr, pHb, MTOK, FF, DD, 1, FF);
        gemm_h<<<gD, blk, GEMM_SMEM_BYTES>>>(
            pHb, pwf2 + fOff, bf2 + vOff, Y,
            Y, nullptr, MTOK, DD, FF, 0, DD);
        float* outl = out + aOff;
        layernorm_row<<<MTOK, blk>>>(Y, g3 + vOff, be3 + vOff, outl, pX);

        Xh = pX;
    }
    (void)in_sizes; (void)n_in; (void)out_size;
}

// round 17
// speedup vs baseline: 1.0017x; 1.0017x over previous
#include <cuda_runtime.h>
#include <cuda_fp16.h>
#include <mma.h>
#include <cstddef>
#include <cstdint>

using namespace nvcuda;

#define LLAYERS 6
#define BB 4
#define NN 1024
#define DD 1024
#define HH 16
#define HDIM 64
#define FF 4096
#define MTOK (BB * NN)      /* 4096 */
#define LN_EPS 1e-5f

// ---------------- scratch (no allocations allowed) ----------------
__device__ float  g_Y[(size_t)MTOK * DD];
__device__ float  g_Y1[(size_t)LLAYERS * MTOK * DD];
__device__ int    g_maskNZ[2];       // [0]=src_mask nonzero, [1]=trg_mask nonzero
// fp16 mirrors
__device__ __half h_wq1[(size_t)LLAYERS * DD * DD];
__device__ __half h_wo1[(size_t)LLAYERS * DD * DD];
__device__ __half h_wq2[(size_t)LLAYERS * DD * DD];
__device__ __half h_wo2[(size_t)LLAYERS * DD * DD];
__device__ __half h_wf1[(size_t)LLAYERS * FF * DD];
__device__ __half h_wf2[(size_t)LLAYERS * DD * FF];
__device__ __half h_feats[(size_t)LLAYERS * MTOK * DD];
__device__ __half h_enc[(size_t)MTOK * DD];
// packed KV weights / biases
__device__ __half h_KV1w[(size_t)LLAYERS * 2 * DD * DD];
__device__ __half h_KV2w[(size_t)LLAYERS * 2 * DD * DD];
__device__ float  g_bKV1[(size_t)LLAYERS * 2 * DD];
__device__ float  g_bKV2[(size_t)LLAYERS * 2 * DD];
// activations
__device__ __half h_KV1[(size_t)LLAYERS * MTOK * 2 * DD];
__device__ __half h_Q1[(size_t)LLAYERS * MTOK * DD];
__device__ __half h_Q2[(size_t)LLAYERS * MTOK * DD];
__device__ __half h_T1[(size_t)LLAYERS * MTOK * DD];
__device__ __half h_Yh1[(size_t)LLAYERS * MTOK * DD];
__device__ __half h_KV2[(size_t)MTOK * 2 * DD];
__device__ __half h_T[(size_t)MTOK * DD];
__device__ __half h_Yh[(size_t)MTOK * DD];
__device__ __half h_X[(size_t)MTOK * DD];
__device__ __half h_Hb[(size_t)MTOK * FF];

// ---------------- cp.async helpers ----------------
__device__ __forceinline__ void cp16(void* sptr, const void* gptr) {
    uint32_t sa = (uint32_t)__cvta_generic_to_shared(sptr);
    asm volatile("cp.async.cg.shared.global [%0], [%1], 16;\n" :: "r"(sa), "l"(gptr));
}
#define CP_COMMIT() asm volatile("cp.async.commit_group;\n" ::: "memory")
#define CP_WAIT_0() asm volatile("cp.async.wait_group 0;\n" ::: "memory")
#define CP_WAIT_1() asm volatile("cp.async.wait_group 1;\n" ::: "memory")

// ---------------- raw mma / ldmatrix helpers (attention) ----------------
__device__ __forceinline__ void mma16816(float* d, const uint32_t* a, const uint32_t* b) {
    asm volatile(
        "mma.sync.aligned.m16n8k16.row.col.f32.f16.f16.f32 "
        "{%0,%1,%2,%3}, {%4,%5,%6,%7}, {%8,%9}, {%0,%1,%2,%3};\n"
        : "+f"(d[0]), "+f"(d[1]), "+f"(d[2]), "+f"(d[3])
        : "r"(a[0]), "r"(a[1]), "r"(a[2]), "r"(a[3]), "r"(b[0]), "r"(b[1]));
}
__device__ __forceinline__ void ldsm4(uint32_t* r, uint32_t addr) {
    asm volatile("ldmatrix.sync.aligned.m8n8.x4.shared.b16 {%0,%1,%2,%3}, [%4];\n"
        : "=r"(r[0]), "=r"(r[1]), "=r"(r[2]), "=r"(r[3]) : "r"(addr));
}
__device__ __forceinline__ void ldsm4t(uint32_t* r, uint32_t addr) {
    asm volatile("ldmatrix.sync.aligned.m8n8.x4.trans.shared.b16 {%0,%1,%2,%3}, [%4];\n"
        : "=r"(r[0]), "=r"(r[1]), "=r"(r[2]), "=r"(r[3]) : "r"(addr));
}
__device__ __forceinline__ uint32_t h2pack(float a, float b) {
    __half2 h = __floats2half2_rn(a, b);
    return *(uint32_t*)&h;
}

// =====================================================================
// Conversion / packing / mask-check kernels
// =====================================================================
__global__ __launch_bounds__(256) void cvt_f2h(
    const float* __restrict__ s, __half* __restrict__ d, long n)
{
    long i = ((long)blockIdx.x * 256 + threadIdx.x) * 8;
    if (i >= n) return;
    float4 a = *(const float4*)(s + i);
    float4 b = *(const float4*)(s + i + 4);
    uint4 u;
    ((__half2*)&u)[0] = __floats2half2_rn(a.x, a.y);
    ((__half2*)&u)[1] = __floats2half2_rn(a.z, a.w);
    ((__half2*)&u)[2] = __floats2half2_rn(b.x, b.y);
    ((__half2*)&u)[3] = __floats2half2_rn(b.z, b.w);
    *(uint4*)(d + i) = u;
}

__global__ __launch_bounds__(256) void pack_w(
    const float* __restrict__ a, const float* __restrict__ b,
    __half* __restrict__ dst, long perL)
{
    long i = ((long)blockIdx.x * 256 + threadIdx.x) * 8;
    long l = i / (2 * perL);
    long r = i - l * 2 * perL;
    const float* src = (r < perL) ? a + l * perL + r : b + l * perL + (r - perL);
    float4 x = *(const float4*)(src);
    float4 y = *(const float4*)(src + 4);
    uint4 u;
    ((__half2*)&u)[0] = __floats2half2_rn(x.x, x.y);
    ((__half2*)&u)[1] = __floats2half2_rn(x.z, x.w);
    ((__half2*)&u)[2] = __floats2half2_rn(y.x, y.y);
    ((__half2*)&u)[3] = __floats2half2_rn(y.z, y.w);
    *(uint4*)(dst + i) = u;
}

__global__ __launch_bounds__(256) void pack_b(
    const float* __restrict__ a, const float* __restrict__ b,
    float* __restrict__ dst, long perL)
{
    long i = ((long)blockIdx.x * 256 + threadIdx.x) * 4;
    long l = i / (2 * perL);
    long r = i - l * 2 * perL;
    const float* src = (r < perL) ? a + l * perL + r : b + l * perL + (r - perL);
    *(float4*)(dst + i) = *(const float4*)src;
}

__global__ void zero_flags() { g_maskNZ[0] = 0; g_maskNZ[1] = 0; }

__global__ __launch_bounds__(256) void mask_check(
    const float* __restrict__ m, long n, int idx)
{
    long i = ((long)blockIdx.x * 256 + threadIdx.x) * 4;
    if (i >= n) return;
    float4 v = *(const float4*)(m + i);
    if (v.x != 0.f || v.y != 0.f || v.z != 0.f || v.w != 0.f)
        atomicOr(&g_maskNZ[idx], 1);
}

// =====================================================================
// f16 TC GEMM — round-10 wmma version (best measured; at register roof).
// =====================================================================
#define GBKH 64
#define GSTH 72
#define GBUFH (128 * GSTH)
#define GEMM_SMEM_BYTES (4 * GBUFH * 2)   /* 73728 B */

__global__ __launch_bounds__(256, 2) void gemm_h(
    const __half* __restrict__ A, const __half* __restrict__ W,
    const float* __restrict__ bias, const float* __restrict__ res,
    float* __restrict__ C, __half* __restrict__ Ch,
    int M, int N, int K, int doRelu, int ldc)
{
    extern __shared__ char dynb[];
    __half* hsm = (__half*)dynb;
    __shared__ float stage[8][16 * 16];

    const int tid  = threadIdx.x;
    const int warp = tid >> 5;
    const int lane = tid & 31;
    const int wm   = warp >> 2;
    const int wn   = warp & 3;

    const __half* Ab = A + (size_t)blockIdx.y * 128 * K;
    const __half* Wb = W + (size_t)blockIdx.x * 128 * K;
    const int KT = K / GBKH;

    wmma::fragment<wmma::accumulator, 16, 16, 16, float> acc[4][2];
#pragma unroll
    for (int i = 0; i < 4; i++)
#pragma unroll
        for (int j = 0; j < 2; j++) wmma::fill_fragment(acc[i][j], 0.f);

    {
        __half* As = hsm;
        __half* Ws = hsm + GBUFH;
#pragma unroll
        for (int t = 0; t < 4; t++) {
            int c = tid + t * 256;
            int row = c >> 3, col8 = c & 7;
            cp16(As + row * GSTH + col8 * 8, Ab + (size_t)row * K + col8 * 8);
            cp16(Ws + row * GSTH + col8 * 8, Wb + (size_t)row * K + col8 * 8);
        }
        CP_COMMIT();
    }

    for (int kt = 0; kt < KT; kt++) {
        if (kt + 1 < KT) {
            __half* As = hsm + ((kt + 1) & 1) * 2 * GBUFH;
            __half* Ws = As + GBUFH;
            const int k0 = (kt + 1) * GBKH;
#pragma unroll
            for (int t = 0; t < 4; t++) {
                int c = tid + t * 256;
                int row = c >> 3, col8 = c & 7;
                cp16(As + row * GSTH + col8 * 8, Ab + (size_t)row * K + k0 + col8 * 8);
                cp16(Ws + row * GSTH + col8 * 8, Wb + (size_t)row * K + k0 + col8 * 8);
            }
            CP_COMMIT();
            CP_WAIT_1();
        } else {
            CP_WAIT_0();
        }
        __syncthreads();

        const __half* As = hsm + (kt & 1) * 2 * GBUFH;
        const __half* Ws = As + GBUFH;
#pragma unroll
        for (int kk = 0; kk < 4; kk++) {
            wmma::fragment<wmma::matrix_a, 16, 16, 16, __half, wmma::row_major> af[4];
            wmma::fragment<wmma::matrix_b, 16, 16, 16, __half, wmma::col_major> bf[2];
#pragma unroll
            for (int i = 0; i < 4; i++)
                wmma::load_matrix_sync(af[i], &As[(wm * 64 + i * 16) * GSTH + kk * 16], GSTH);
#pragma unroll
            for (int j = 0; j < 2; j++)
                wmma::load_matrix_sync(bf[j], &Ws[(wn * 32 + j * 16) * GSTH + kk * 16], GSTH);
#pragma unroll
            for (int i = 0; i < 4; i++)
#pragma unroll
                for (int j = 0; j < 2; j++)
                    wmma::mma_sync(acc[i][j], af[i], bf[j], acc[i][j]);
        }
        __syncthreads();
    }

#pragma unroll
    for (int i = 0; i < 4; i++) {
#pragma unroll
        for (int j = 0; j < 2; j++) {
            wmma::store_matrix_sync(stage[warp], acc[i][j], 16, wmma::mem_row_major);
            __syncwarp();
            int r0 = blockIdx.y * 128 + wm * 64 + i * 16;
            int c0 = blockIdx.x * 128 + wn * 32 + j * 16;
#pragma unroll
            for (int e = 0; e < 2; e++) {
                int idx = lane + e * 32;
                int rr  = idx >> 2;
                int cc  = (idx & 3) << 2;
                float4 v  = *(float4*)&stage[warp][rr * 16 + cc];
                float4 b4 = *(const float4*)(bias + c0 + cc);
                v.x += b4.x; v.y += b4.y; v.z += b4.z; v.w += b4.w;
                size_t row = (size_t)(r0 + rr);
                if (res) {
                    float4 r = *(const float4*)(res + row * ldc + c0 + cc);
                    v.x += r.x; v.y += r.y; v.z += r.z; v.w += r.w;
                }
                if (doRelu) {
                    v.x = fmaxf(v.x, 0.f); v.y = fmaxf(v.y, 0.f);
                    v.z = fmaxf(v.z, 0.f); v.w = fmaxf(v.w, 0.f);
                }
                if (C) *(float4*)(C + row * ldc + c0 + cc) = v;
                if (Ch) {
                    uint2 u;
                    ((__half2*)&u)[0] = __floats2half2_rn(v.x, v.y);
                    ((__half2*)&u)[1] = __floats2half2_rn(v.z, v.w);
                    *(uint2*)(Ch + row * ldc + c0 + cc) = u;
                }
            }
            __syncwarp();
        }
    }
}

// =====================================================================
// Flash attention v5 (round-15): register-resident FA2 + mask elision.
// grid: (N/128, B*H)
// =====================================================================
#define AQ_ST 72
#define ATQ_OFF 0
#define ATK_OFF(s) (18432 + (s) * 9216)
#define ATV_OFF(s) (46080 + (s) * 9216)
#define ATT_SMEM_BYTES 73728

__global__ __launch_bounds__(256, 2) void attn_h(
    const __half* __restrict__ Q, const __half* __restrict__ Kb,
    const __half* __restrict__ V, __half* __restrict__ T,
    const float* __restrict__ mask, int ldkv,
    const int* __restrict__ nzflag)
{
    extern __shared__ char dynb[];
    const uint32_t sb = (uint32_t)__cvta_generic_to_shared(dynb);

    const int z = blockIdx.y;
    const int b = z >> 4, hh = z & 15;
    const __half* Qz = Q  + (size_t)b * NN * DD   + hh * HDIM;
    const __half* Kz = Kb + (size_t)b * NN * ldkv + hh * HDIM;
    const __half* Vz = V  + (size_t)b * NN * ldkv + hh * HDIM;
    __half*       Tz = T  + (size_t)b * NN * DD   + hh * HDIM;
    const int i0 = blockIdx.x * 128;

    const int tid  = threadIdx.x;
    const int warp = tid >> 5;
    const int lane = tid & 31;
    const int g    = lane >> 2;
    const int t    = lane & 3;
    const int q    = lane >> 3;
    const int qr   = lane & 7;

    const int useMask = *nzflag;

    const uint32_t qlane = (uint32_t)(((q & 1) * 8 + qr + warp * 16) * 144 + (q >> 1) * 16);
    const uint32_t klane = (uint32_t)(((q >> 1) * 8 + qr) * 144 + (q & 1) * 16);
    const uint32_t vlane = (uint32_t)(((q & 1) * 8 + qr) * 144 + (q >> 1) * 16);

    const float* mrow0 = mask + (size_t)(i0 + warp * 16 + g) * NN;
    const float* mrow1 = mrow0 + 8 * NN;

    {
        __half* Qs = (__half*)(dynb + ATQ_OFF);
#pragma unroll
        for (int c0 = 0; c0 < 4; c0++) {
            int c = tid + c0 * 256;
            int row = c >> 3, col8 = c & 7;
            cp16(Qs + row * AQ_ST + col8 * 8, Qz + (size_t)(i0 + row) * DD + col8 * 8);
        }
        __half* Ks = (__half*)(dynb + ATK_OFF(0));
        __half* Vs = (__half*)(dynb + ATV_OFF(0));
#pragma unroll
        for (int c0 = 0; c0 < 2; c0++) {
            int c = tid + c0 * 256;
            int row = c >> 3, col8 = c & 7;
            cp16(Ks + row * AQ_ST + col8 * 8, Kz + (size_t)row * ldkv + col8 * 8);
            cp16(Vs + row * AQ_ST + col8 * 8, Vz + (size_t)row * ldkv + col8 * 8);
        }
        CP_COMMIT();
        Ks = (__half*)(dynb + ATK_OFF(1));
        Vs = (__half*)(dynb + ATV_OFF(1));
#pragma unroll
        for (int c0 = 0; c0 < 2; c0++) {
            int c = tid + c0 * 256;
            int row = c >> 3, col8 = c & 7;
            cp16(Ks + row * AQ_ST + col8 * 8, Kz + (size_t)(64 + row) * ldkv + col8 * 8);
            cp16(Vs + row * AQ_ST + col8 * 8, Vz + (size_t)(64 + row) * ldkv + col8 * 8);
        }
        CP_COMMIT();
    }

    CP_WAIT_1();
    __syncthreads();

    uint32_t qa[4][4];
#pragma unroll
    for (int kk = 0; kk < 4; kk++)
        ldsm4(qa[kk], sb + ATQ_OFF + qlane + kk * 32);

    float o[8][4];
#pragma unroll
    for (int i = 0; i < 8; i++) { o[i][0] = o[i][1] = o[i][2] = o[i][3] = 0.f; }
    float m0 = -1e30f, m1 = -1e30f, sr0 = 0.f, sr1 = 0.f;

    const int J = NN / 64;
    for (int j0 = 0; j0 < J; j0++) {
        if (j0 > 0) {
            if (j0 + 1 < J) { CP_WAIT_1(); } else { CP_WAIT_0(); }
            __syncthreads();
        }
        if (j0 + 2 < J) {
            const int st = (j0 + 2) % 3;
            __half* Ks = (__half*)(dynb + ATK_OFF(st));
            __half* Vs = (__half*)(dynb + ATV_OFF(st));
            const size_t rbase = (size_t)(j0 + 2) * 64;
#pragma unroll
            for (int c0 = 0; c0 < 2; c0++) {
                int c = tid + c0 * 256;
                int row = c >> 3, col8 = c & 7;
                cp16(Ks + row * AQ_ST + col8 * 8, Kz + (rbase + row) * ldkv + col8 * 8);
                cp16(Vs + row * AQ_ST + col8 * 8, Vz + (rbase + row) * ldkv + col8 * 8);
            }
            CP_COMMIT();
        }

        const uint32_t ksb = sb + ATK_OFF(j0 % 3);
        const uint32_t vsb = sb + ATV_OFF(j0 % 3);

        float s[8][4];
#pragma unroll
        for (int i = 0; i < 8; i++) { s[i][0] = s[i][1] = s[i][2] = s[i][3] = 0.f; }
#pragma unroll
        for (int nt2 = 0; nt2 < 4; nt2++) {
#pragma unroll
            for (int kk = 0; kk < 4; kk++) {
                uint32_t kb[4];
                ldsm4(kb, ksb + (uint32_t)(nt2 * 2304 + kk * 32) + klane);
                mma16816(s[2 * nt2],     qa[kk], kb);
                mma16816(s[2 * nt2 + 1], qa[kk], kb + 2);
            }
        }

        float mx0 = m0, mx1 = m1;
        if (useMask) {
#pragma unroll
            for (int nt = 0; nt < 8; nt++) {
                int col = j0 * 64 + nt * 8 + 2 * t;
                float2 k0 = *(const float2*)(mrow0 + col);
                float2 k1 = *(const float2*)(mrow1 + col);
                s[nt][0] = fmaf(s[nt][0], 0.125f, k0.x);
                s[nt][1] = fmaf(s[nt][1], 0.125f, k0.y);
                s[nt][2] = fmaf(s[nt][2], 0.125f, k1.x);
                s[nt][3] = fmaf(s[nt][3], 0.125f, k1.y);
                mx0 = fmaxf(mx0, fmaxf(s[nt][0], s[nt][1]));
                mx1 = fmaxf(mx1, fmaxf(s[nt][2], s[nt][3]));
            }
        } else {
#pragma unroll
            for (int nt = 0; nt < 8; nt++) {
                s[nt][0] *= 0.125f; s[nt][1] *= 0.125f;
                s[nt][2] *= 0.125f; s[nt][3] *= 0.125f;
                mx0 = fmaxf(mx0, fmaxf(s[nt][0], s[nt][1]));
                mx1 = fmaxf(mx1, fmaxf(s[nt][2], s[nt][3]));
            }
        }
        mx0 = fmaxf(mx0, __shfl_xor_sync(0xffffffffu, mx0, 1));
        mx0 = fmaxf(mx0, __shfl_xor_sync(0xffffffffu, mx0, 2));
        mx1 = fmaxf(mx1, __shfl_xor_sync(0xffffffffu, mx1, 1));
        mx1 = fmaxf(mx1, __shfl_xor_sync(0xffffffffu, mx1, 2));
        const float c0 = __expf(m0 - mx0);
        const float c1 = __expf(m1 - mx1);

        uint32_t pa[4][4];
        float sum0 = 0.f, sum1 = 0.f;
#pragma unroll
        for (int nt = 0; nt < 8; nt++) {
            float p0 = __expf(s[nt][0] - mx0);
            float p1 = __expf(s[nt][1] - mx0);
            float p2 = __expf(s[nt][2] - mx1);
            float p3 = __expf(s[nt][3] - mx1);
            sum0 += p0 + p1; sum1 += p2 + p3;
            pa[nt >> 1][(nt & 1) * 2 + 0] = h2pack(p0, p1);
            pa[nt >> 1][(nt & 1) * 2 + 1] = h2pack(p2, p3);
        }
        sum0 += __shfl_xor_sync(0xffffffffu, sum0, 1);
        sum0 += __shfl_xor_sync(0xffffffffu, sum0, 2);
        sum1 += __shfl_xor_sync(0xffffffffu, sum1, 1);
        sum1 += __shfl_xor_sync(0xffffffffu, sum1, 2);
        sr0 = sr0 * c0 + sum0;
        sr1 = sr1 * c1 + sum1;
        m0 = mx0; m1 = mx1;
#pragma unroll
        for (int nt = 0; nt < 8; nt++) {
            o[nt][0] *= c0; o[nt][1] *= c0;
            o[nt][2] *= c1; o[nt][3] *= c1;
        }

#pragma unroll
        for (int nt2 = 0; nt2 < 4; nt2++) {
#pragma unroll
            for (int kt = 0; kt < 4; kt++) {
                uint32_t vb[4];
                ldsm4t(vb, vsb + (uint32_t)(kt * 2304 + nt2 * 32) + vlane);
                mma16816(o[2 * nt2],     pa[kt], vb);
                mma16816(o[2 * nt2 + 1], pa[kt], vb + 2);
            }
        }
    }

    const float inv0 = 1.f / sr0;
    const float inv1 = 1.f / sr1;
    __half* tr0 = Tz + (size_t)(i0 + warp * 16 + g) * DD + 2 * t;
    __half* tr1 = tr0 + 8 * DD;
#pragma unroll
    for (int nt = 0; nt < 8; nt++) {
        uint32_t u0 = h2pack(o[nt][0] * inv0, o[nt][1] * inv0);
        uint32_t u1 = h2pack(o[nt][2] * inv1, o[nt][3] * inv1);
        *(uint32_t*)(tr0 + nt * 8) = u0;
        *(uint32_t*)(tr1 + nt * 8) = u1;
    }
}

// =====================================================================
// LayerNorm v2 (round-14): shuffle reductions, 1 barrier.
// =====================================================================
__global__ __launch_bounds__(256) void layernorm_row(
    const float* __restrict__ X, const float* __restrict__ g,
    const float* __restrict__ bta, float* __restrict__ Y,
    __half* __restrict__ Yh)
{
    __shared__ float psum[8], psq[8];
    const size_t base = (size_t)blockIdx.x * DD;
    const int tid  = threadIdx.x;
    const int warp = tid >> 5;
    const int lane = tid & 31;
    float4 v = *(const float4*)(X + base + tid * 4);

    float s  = v.x + v.y + v.z + v.w;
    float sq = v.x * v.x + v.y * v.y + v.z * v.z + v.w * v.w;
#pragma unroll
    for (int o = 16; o > 0; o >>= 1) {
        s  += __shfl_xor_sync(0xffffffffu, s,  o);
        sq += __shfl_xor_sync(0xffffffffu, sq, o);
    }
    if (lane == 0) { psum[warp] = s; psq[warp] = sq; }
    __syncthreads();

    float ts = 0.f, tq = 0.f;
#pragma unroll
    for (int w = 0; w < 8; w++) { ts += psum[w]; tq += psq[w]; }
    const float mean = ts * (1.f / DD);
    const float var  = tq * (1.f / DD) - mean * mean;
    const float inv  = rsqrtf(var + LN_EPS);

    float4 gg = *(const float4*)(g + tid * 4);
    float4 bb = *(const float4*)(bta + tid * 4);
    float4 o;
    o.x = (v.x - mean) * inv * gg.x + bb.x;
    o.y = (v.y - mean) * inv * gg.y + bb.y;
    o.z = (v.z - mean) * inv * gg.z + bb.z;
    o.w = (v.w - mean) * inv * gg.w + bb.w;
    *(float4*)(Y + base + tid * 4) = o;
    if (Yh) {
        uint2 u;
        ((__half2*)&u)[0] = __floats2half2_rn(o.x, o.y);
        ((__half2*)&u)[1] = __floats2half2_rn(o.z, o.w);
        *(uint2*)(Yh + base + tid * 4) = u;
    }
}

// =====================================================================
// Host orchestration: round-15 structure (best measured) + KV2 hoist.
// =====================================================================
static inline void cvt0(const float* src, __half* dst, long n, cudaStream_t st) {
    cvt_f2h<<<(unsigned)(n / 2048), 256, 0, st>>>(src, dst, n);
}

extern "C" void kernel_launch(void* const* d_in, const int* in_sizes, int n_in,
                              void* d_out, int out_size)
{
    const float* feats    = (const float*)d_in[0];
    const float* enc      = (const float*)d_in[1];
    const float* trg_mask = (const float*)d_in[2];
    const float* src_mask = (const float*)d_in[3];
    const float* wq1 = (const float*)d_in[4];  const float* bq1 = (const float*)d_in[5];
    const float* wk1 = (const float*)d_in[6];  const float* bk1 = (const float*)d_in[7];
    const float* wv1 = (const float*)d_in[8];  const float* bv1 = (const float*)d_in[9];
    const float* wo1 = (const float*)d_in[10]; const float* bo1 = (const float*)d_in[11];
    const float* wq2 = (const float*)d_in[12]; const float* bq2 = (const float*)d_in[13];
    const float* wk2 = (const float*)d_in[14]; const float* bk2 = (const float*)d_in[15];
    const float* wv2 = (const float*)d_in[16]; const float* bv2 = (const float*)d_in[17];
    const float* wo2 = (const float*)d_in[18]; const float* bo2 = (const float*)d_in[19];
    const float* wf1 = (const float*)d_in[20]; const float* bf1 = (const float*)d_in[21];
    const float* wf2 = (const float*)d_in[22]; const float* bf2 = (const float*)d_in[23];
    const float* g1  = (const float*)d_in[24]; const float* be1 = (const float*)d_in[25];
    const float* g2  = (const float*)d_in[26]; const float* be2 = (const float*)d_in[27];
    const float* g3  = (const float*)d_in[28]; const float* be3 = (const float*)d_in[29];
    float* out = (float*)d_out;

    static int init_done = 0;
    static cudaStream_t s2;
    static cudaEvent_t evF, evA;
    static cudaEvent_t evL[LLAYERS];
    if (!init_done) {
        cudaFuncSetAttribute(gemm_h,
            cudaFuncAttributeMaxDynamicSharedMemorySize, GEMM_SMEM_BYTES);
        cudaFuncSetAttribute(attn_h,
            cudaFuncAttributeMaxDynamicSharedMemorySize, ATT_SMEM_BYTES);
        int prLo = 0, prHi = 0;
        cudaDeviceGetStreamPriorityRange(&prLo, &prHi);
        cudaStreamCreateWithPriority(&s2, cudaStreamNonBlocking, prLo);
        cudaEventCreateWithFlags(&evF, cudaEventDisableTiming);
        cudaEventCreateWithFlags(&evA, cudaEventDisableTiming);
        for (int l = 0; l < LLAYERS; l++)
            cudaEventCreateWithFlags(&evL[l], cudaEventDisableTiming);
        init_done = 1;
    }

    float *Y, *Y1, *pbKV1, *pbKV2;
    int* pNZ;
    cudaGetSymbolAddress((void**)&Y,  g_Y);
    cudaGetSymbolAddress((void**)&Y1, g_Y1);
    cudaGetSymbolAddress((void**)&pbKV1, g_bKV1);
    cudaGetSymbolAddress((void**)&pbKV2, g_bKV2);
    cudaGetSymbolAddress((void**)&pNZ, g_maskNZ);
    __half *pwq1, *pwo1, *pwq2, *pwo2, *pwf1, *pwf2, *pfeats, *penc;
    __half *pKV1w, *pKV2w, *pKV1, *pQ1, *pQ2, *pT1, *pYh1, *pKV2, *pT, *pYh, *pX, *pHb;
    cudaGetSymbolAddress((void**)&pwq1, h_wq1);
    cudaGetSymbolAddress((void**)&pwo1, h_wo1);
    cudaGetSymbolAddress((void**)&pwq2, h_wq2);
    cudaGetSymbolAddress((void**)&pwo2, h_wo2);
    cudaGetSymbolAddress((void**)&pwf1, h_wf1);
    cudaGetSymbolAddress((void**)&pwf2, h_wf2);
    cudaGetSymbolAddress((void**)&pfeats, h_feats);
    cudaGetSymbolAddress((void**)&penc, h_enc);
    cudaGetSymbolAddress((void**)&pKV1w, h_KV1w);
    cudaGetSymbolAddress((void**)&pKV2w, h_KV2w);
    cudaGetSymbolAddress((void**)&pKV1, h_KV1);
    cudaGetSymbolAddress((void**)&pQ1, h_Q1);
    cudaGetSymbolAddress((void**)&pQ2, h_Q2);
    cudaGetSymbolAddress((void**)&pT1, h_T1);
    cudaGetSymbolAddress((void**)&pYh1, h_Yh1);
    cudaGetSymbolAddress((void**)&pKV2, h_KV2);
    cudaGetSymbolAddress((void**)&pT, h_T);
    cudaGetSymbolAddress((void**)&pYh, h_Yh);
    cudaGetSymbolAddress((void**)&pX, h_X);
    cudaGetSymbolAddress((void**)&pHb, h_Hb);

    const long nDD1 = (long)DD * DD;
    const long nMD1 = (long)MTOK * DD;
    const long nDD = (long)LLAYERS * nDD1;
    const long nFD = (long)LLAYERS * FF * DD;
    const long nMask = (long)NN * NN;

    // ---- mask pre-pass + minimal pre-fork conversions (stream 0) ----
    zero_flags<<<1, 1>>>();
    mask_check<<<(unsigned)(nMask / 1024), 256>>>(src_mask, nMask, 0);
    mask_check<<<(unsigned)(nMask / 1024), 256>>>(trg_mask, nMask, 1);
    cvt0(enc, penc, nMD1, 0);
    cvt0(feats, pfeats, nMD1, 0);
    cvt0(wq1, pwq1, nDD1, 0);
    cvt0(wo1, pwo1, nDD1, 0);
    cvt0(wq2, pwq2, nDD1, 0);
    pack_w<<<(unsigned)(2 * nDD1 / 2048), 256>>>(wk1, wv1, pKV1w, nDD1);
    pack_b<<<(unsigned)(2 * LLAYERS * DD / 1024), 256>>>(bk1, bv1, pbKV1, DD);

    dim3 blk(256);
    dim3 gD(DD / 128, MTOK / 128);
    dim3 gKV(2 * DD / 128, MTOK / 128);
    dim3 gF(FF / 128, MTOK / 128);
    dim3 gA(NN / 128, BB * HH);

    // ---- fork ----
    cudaEventRecord(evF, 0);
    cudaStreamWaitEvent(s2, evF, 0);

    // A-rest conversions (layers 1..5) on stream 0, under phase-A layer 0
    cvt0(feats + nMD1, pfeats + nMD1, (LLAYERS - 1) * nMD1, 0);
    cvt0(wq1 + nDD1, pwq1 + nDD1, (LLAYERS - 1) * nDD1, 0);
    cvt0(wo1 + nDD1, pwo1 + nDD1, (LLAYERS - 1) * nDD1, 0);
    cvt0(wq2 + nDD1, pwq2 + nDD1, (LLAYERS - 1) * nDD1, 0);
    pack_w<<<(unsigned)(2 * (LLAYERS - 1) * nDD1 / 2048), 256>>>(
        wk1 + nDD1, wv1 + nDD1, pKV1w + 2 * nDD1, nDD1);
    cudaEventRecord(evA, 0);

    // ---- phase A (attn1 branch + q2 precompute) on s2 ----
    for (int l = 0; l < LLAYERS; l++) {
        const size_t wOff = (size_t)l * DD * DD;
        const size_t vOff = (size_t)l * DD;
        const size_t aOff = (size_t)l * MTOK * DD;
        const size_t kOff = (size_t)l * MTOK * 2 * DD;

        if (l == 1) cudaStreamWaitEvent(s2, evA, 0);

        gemm_h<<<gD, blk, GEMM_SMEM_BYTES, s2>>>(
            pfeats + aOff, pwq1 + wOff, bq1 + vOff, nullptr,
            nullptr, pQ1 + aOff, MTOK, DD, DD, 0, DD);
        gemm_h<<<gKV, blk, GEMM_SMEM_BYTES, s2>>>(
            penc, pKV1w + 2 * wOff, pbKV1 + 2 * vOff, nullptr,
            nullptr, pKV1 + kOff, MTOK, 2 * DD, DD, 0, 2 * DD);
        attn_h<<<gA, blk, ATT_SMEM_BYTES, s2>>>(
            pQ1 + aOff, pKV1 + kOff, pKV1 + kOff + DD, pT1 + aOff,
            src_mask, 2 * DD, pNZ + 0);
        gemm_h<<<gD, blk, GEMM_SMEM_BYTES, s2>>>(
            pT1 + aOff, pwo1 + wOff, bo1 + vOff, feats + aOff,
            Y1 + aOff, nullptr, MTOK, DD, DD, 0, DD);
        layernorm_row<<<MTOK, blk, 0, s2>>>(
            Y1 + aOff, g1 + vOff, be1 + vOff, Y1 + aOff, pYh1 + aOff);
        gemm_h<<<gD, blk, GEMM_SMEM_BYTES, s2>>>(
            pYh1 + aOff, pwq2 + wOff, bq2 + vOff, nullptr,
            nullptr, pQ2 + aOff, MTOK, DD, DD, 0, DD);
        cudaEventRecord(evL[l], s2);
    }

    // ---- B-set conversions on stream 0 (overlap phase A) ----
    cvt0(wo2, pwo2, nDD, 0);
    cvt0(wf1, pwf1, nFD, 0);
    cvt0(wf2, pwf2, nFD, 0);
    pack_w<<<(unsigned)(2 * nDD / 2048), 256>>>(wk2, wv2, pKV2w, nDD1);
    pack_b<<<(unsigned)(2 * LLAYERS * DD / 1024), 256>>>(bk2, bv2, pbKV2, DD);

    // ---- phase B: serial decoder chain on stream 0 ----
    const __half* Xh = penc;
    for (int l = 0; l < LLAYERS; l++) {
        const size_t wOff = (size_t)l * DD * DD;
        const size_t fOff = (size_t)l * FF * DD;
        const size_t vOff = (size_t)l * DD;
        const size_t aOff = (size_t)l * MTOK * DD;

        // KV2 depends only on the previous layer's output — issue it
        // BEFORE waiting for phase A's layer-l results (free overlap).
        gemm_h<<<gKV, blk, GEMM_SMEM_BYTES>>>(
            Xh, pKV2w + 2 * wOff, pbKV2 + 2 * vOff, nullptr,
            nullptr, pKV2, MTOK, 2 * DD, DD, 0, 2 * DD);

        cudaStreamWaitEvent(0, evL[l], 0);

        attn_h<<<gA, blk, ATT_SMEM_BYTES>>>(
            pQ2 + aOff, pKV2, pKV2 + DD, pT, trg_mask, 2 * DD, pNZ + 1);
        gemm_h<<<gD, blk, GEMM_SMEM_BYTES>>>(
            pT, pwo2 + wOff, bo2 + vOff, Y1 + aOff,
            Y, nullptr, MTOK, DD, DD, 0, DD);
        layernorm_row<<<MTOK, blk>>>(Y, g2 + vOff, be2 + vOff, Y, pYh);

        gemm_h<<<gF, blk, GEMM_SMEM_BYTES>>>(
            pYh, pwf1 + fOff, bf1 + (size_t)l * FF, nullptr,
            nullptr, pHb, MTOK, FF, DD, 1, FF);
        gemm_h<<<gD, blk, GEMM_SMEM_BYTES>>>(
            pHb, pwf2 + fOff, bf2 + vOff, Y,
            Y, nullptr, MTOK, DD, FF, 0, DD);
        float* outl = out + aOff;
        layernorm_row<<<MTOK, blk>>>(Y, g3 + vOff, be3 + vOff, outl, pX);

        Xh = pX;
    }
    (void)in_sizes; (void)n_in; (void)out_size;
}